// round 2
// baseline (speedup 1.0000x reference)
#include <cuda_runtime.h>
#include <math.h>

// Problem constants (fixed shapes)
#define NN 20000
#define EE 320000
#define CC 32
#define LMM 16
#define TT 2

// Output layout offsets (floats)
#define O_NSUM 0
#define O_NC   (NN*100)                  //  2,000,000
#define O_ESUM (NN*100 + NN*100*TT)      //  6,000,000
#define O_EC   (O_ESUM + (size_t)EE*100) // 38,000,000

// ---------------- scratch (static device arrays; no allocation) ----------------
static __device__ float g_Y [(size_t)EE*16];
static __device__ float g_eb[(size_t)EE*8];
static __device__ float g_R4[(size_t)EE*128];
static __device__ float g_h0[NN*32];
static __device__ float g_nf [(size_t)NN*512];   // [n][c][L]
static __device__ float g_agg[(size_t)NN*512];   // [n][c][L]
static __device__ float g_nf0[NN*32];
static __device__ int   g_deg[NN];
static __device__ int   g_off[NN+1];
static __device__ int   g_cur[NN];
static __device__ int   g_eids[EE];

__device__ __forceinline__ float silu_f(float x) { return x / (1.f + __expf(-x)); }

// ---------------- 0: zero degree ----------------
__global__ void k_zero_deg() {
    int i = blockIdx.x*blockDim.x + threadIdx.x;
    if (i < NN) g_deg[i] = 0;
}

// ---------------- 1: edge geometry: Y, eb(=bessel*cutoff), degree histogram ----------------
__global__ void k_geom(const float* __restrict__ pos, const float* __restrict__ shifts,
                       const int* __restrict__ ei) {
    int e = blockIdx.x*blockDim.x + threadIdx.x;
    if (e >= EE) return;
    int s = ei[e], d = ei[EE+e];
    float vx = pos[d*3+0] - pos[s*3+0] + shifts[e*3+0];
    float vy = pos[d*3+1] - pos[s*3+1] + shifts[e*3+1];
    float vz = pos[d*3+2] - pos[s*3+2] + shifts[e*3+2];
    float r = sqrtf(vx*vx + vy*vy + vz*vz) + 1e-9f;
    float inr = 1.f/r;
    float x = vx*inr, y = vy*inr, z = vz*inr;
    const float s3=1.7320508075688772f, s5=2.23606797749979f, s15=3.872983346207417f,
                s7=2.6457513110645907f, c358=2.091650066335189f, c105=10.246950765959598f,
                c218=1.6201851746019651f;
    float z2=z*z, x2=x*x, y2=y*y;
    float Y[16];
    Y[0]=1.f;               Y[1]=s3*x;              Y[2]=s3*y;               Y[3]=s3*z;
    Y[4]=s15*x*y;           Y[5]=s15*y*z;           Y[6]=0.5f*s5*(3.f*z2-1.f); Y[7]=s15*x*z;
    Y[8]=0.5f*s15*(x2-y2);  Y[9]=c358*y*(3.f*x2-y2); Y[10]=c105*x*y*z;
    Y[11]=c218*y*(5.f*z2-1.f); Y[12]=0.5f*s7*z*(5.f*z2-3.f); Y[13]=c218*x*(5.f*z2-1.f);
    Y[14]=0.5f*c105*z*(x2-y2); Y[15]=c358*x*(x2-3.f*y2);
    float4* yo = (float4*)(g_Y + (size_t)e*16);
    yo[0]=make_float4(Y[0],Y[1],Y[2],Y[3]);
    yo[1]=make_float4(Y[4],Y[5],Y[6],Y[7]);
    yo[2]=make_float4(Y[8],Y[9],Y[10],Y[11]);
    yo[3]=make_float4(Y[12],Y[13],Y[14],Y[15]);
    // cutoff P=5: 1 - 21 x^5 + 35 x^6 - 15 x^7
    float xr = r*0.2f;
    float cut = 0.f;
    if (xr < 1.f) {
        float x2c = xr*xr;
        float x5 = x2c*x2c*xr;
        cut = 1.f - 21.f*x5 + 35.f*x5*xr - 15.f*x5*x2c;
    }
    float pref = 0.6324555320336759f * inr * cut; // sqrt(2/5)/r * cutoff
    float w = 0.6283185307179586f * r;            // pi/5 * r
    float eb[8];
#pragma unroll
    for (int n=0;n<8;n++) eb[n] = pref * sinf((float)(n+1)*w);
    float4* eo = (float4*)(g_eb + (size_t)e*8);
    eo[0]=make_float4(eb[0],eb[1],eb[2],eb[3]);
    eo[1]=make_float4(eb[4],eb[5],eb[6],eb[7]);
    atomicAdd(&g_deg[d], 1);
}

// ---------------- 2: exclusive scan of degrees (single block) ----------------
__global__ void k_scan() {
    __shared__ int sdata[1024];
    __shared__ int s_carry;
    int tid = threadIdx.x;
    if (tid == 0) { s_carry = 0; g_off[0] = 0; }
    __syncthreads();
    for (int base = 0; base < NN; base += 1024) {
        int i = base + tid;
        int v = (i < NN) ? g_deg[i] : 0;
        sdata[tid] = v;
        __syncthreads();
        for (int o = 1; o < 1024; o <<= 1) {
            int add = (tid >= o) ? sdata[tid - o] : 0;
            __syncthreads();
            sdata[tid] += add;
            __syncthreads();
        }
        int carry = s_carry;
        if (i < NN) {
            int incl = sdata[tid];
            g_off[i+1] = carry + incl;
            g_cur[i]   = carry + incl - v;
        }
        __syncthreads();
        if (tid == 0) s_carry = carry + sdata[1023];
        __syncthreads();
    }
}

// ---------------- 3: scatter edge ids into CSR ----------------
__global__ void k_scatter(const int* __restrict__ ei) {
    int e = blockIdx.x*blockDim.x + threadIdx.x;
    if (e >= EE) return;
    int d = ei[EE+e];
    int pos = atomicAdd(&g_cur[d], 1);
    g_eids[pos] = e;
}

// ---------------- 4: init node features ----------------
__global__ void k_init_nf(const float* __restrict__ W_emb, const int* __restrict__ types) {
    int idx = blockIdx.x*blockDim.x + threadIdx.x;
    if (idx >= NN*32) return;
    int n = idx >> 5, c = idx & 31;
    float v = W_emb[types[n]*32 + c];
    float4* o = (float4*)(g_nf + (size_t)n*512 + c*16);
    o[0] = make_float4(v,0.f,0.f,0.f);
    o[1] = make_float4(0.f,0.f,0.f,0.f);
    o[2] = o[1]; o[3] = o[1];
}

// ---------------- 5: h0[n,k] = sum_c nf[n,c,0] * W_up[t][c,k] (warp per node) ----------------
__global__ void k_h0(const float* __restrict__ W_up, int t) {
    int gw = (blockIdx.x*blockDim.x + threadIdx.x) >> 5;
    if (gw >= NN) return;
    int k = threadIdx.x & 31;
    const float* wu = W_up + t*1024;
    const float* nf = g_nf + (size_t)gw*512;
    float a = 0.f;
#pragma unroll
    for (int c=0;c<32;c++) a += nf[c*16] * wu[c*32 + k];
    g_h0[gw*32 + k] = a;
}

// ---------------- 6: radial MLP (thread per edge, weights + x in dyn smem) ----------------
__global__ void k_radial(const float* __restrict__ rW1, const float* __restrict__ rb1,
                         const float* __restrict__ rW2, const float* __restrict__ rb2,
                         const float* __restrict__ rW3, int t) {
    extern __shared__ float sh[];
    float* s_w1 = sh;            // 512
    float* s_b1 = s_w1 + 512;    // 64
    float* s_w2 = s_b1 + 64;     // 4096
    float* s_b2 = s_w2 + 4096;   // 64
    float* s_w3 = s_b2 + 64;     // 8192
    float* s_x  = s_w3 + 8192;   // 64*129
    int tid = threadIdx.x;
    for (int i=tid;i<512;i+=128)  s_w1[i]=rW1[t*512+i];
    for (int i=tid;i<64;i+=128)   s_b1[i]=rb1[t*64+i];
    for (int i=tid;i<4096;i+=128) s_w2[i]=rW2[t*4096+i];
    for (int i=tid;i<64;i+=128)   s_b2[i]=rb2[t*64+i];
    for (int i=tid;i<8192;i+=128) s_w3[i]=rW3[t*8192+i];
    __syncthreads();

    int e = blockIdx.x*128 + tid;   // EE divisible by 128
    const float4* ebv = (const float4*)(g_eb + (size_t)e*8);
    float4 e0 = ebv[0], e1 = ebv[1];
    float ebl[8] = {e0.x,e0.y,e0.z,e0.w,e1.x,e1.y,e1.z,e1.w};

    // layer 1: 8 -> 64, silu, to s_x
    for (int j=0;j<64;j++) {
        float a = s_b1[j];
#pragma unroll
        for (int b=0;b<8;b++) a += ebl[b]*s_w1[b*64+j];
        s_x[j*129+tid] = silu_f(a);
    }
    // layer 2: 64 -> 64 (acc in regs), silu, back to s_x
    float acc[64];
#pragma unroll
    for (int j=0;j<64;j++) acc[j] = s_b2[j];
    for (int i=0;i<64;i++) {
        float v = s_x[i*129+tid];
        const float4* w = (const float4*)(s_w2 + i*64);
#pragma unroll
        for (int j=0;j<16;j++) {
            float4 ww = w[j];
            acc[4*j+0] += v*ww.x; acc[4*j+1] += v*ww.y;
            acc[4*j+2] += v*ww.z; acc[4*j+3] += v*ww.w;
        }
    }
#pragma unroll
    for (int j=0;j<64;j++) s_x[j*129+tid] = silu_f(acc[j]);
    // layer 3: 64 -> 128, two halves of 64 outputs
#pragma unroll 2
    for (int half=0; half<2; half++) {
        float o[64];
#pragma unroll
        for (int j=0;j<64;j++) o[j]=0.f;
        for (int i=0;i<64;i++) {
            float v = s_x[i*129+tid];
            const float4* w = (const float4*)(s_w3 + i*128 + half*64);
#pragma unroll
            for (int j=0;j<16;j++) {
                float4 ww = w[j];
                o[4*j+0] += v*ww.x; o[4*j+1] += v*ww.y;
                o[4*j+2] += v*ww.z; o[4*j+3] += v*ww.w;
            }
        }
        float4* op = (float4*)(g_R4 + (size_t)e*128 + half*64);
#pragma unroll
        for (int q=0;q<16;q++) op[q] = make_float4(o[4*q],o[4*q+1],o[4*q+2],o[4*q+3]);
    }
}

// ---------------- 7: aggregation gather (warp per dst node, lane = channel) ----------------
__global__ void k_gather(const int* __restrict__ ei) {
    int gw = (blockIdx.x*blockDim.x + threadIdx.x) >> 5;
    if (gw >= NN) return;
    int c = threadIdx.x & 31;
    float acc[16];
#pragma unroll
    for (int L=0;L<16;L++) acc[L]=0.f;
    int beg = g_off[gw], end = g_off[gw+1];
    for (int idx = beg; idx < end; idx++) {
        int e = g_eids[idx];
        int s = ei[e];
        float hs = g_h0[s*32 + c];
        const float4* yv = (const float4*)(g_Y + (size_t)e*16);
        float4 y0=yv[0], y1=yv[1], y2=yv[2], y3=yv[3];
        const float* R = g_R4 + (size_t)e*128;
        float h0v = hs*R[c], h1v = hs*R[32+c], h2v = hs*R[64+c], h3v = hs*R[96+c];
        acc[0]+=h0v*y0.x; acc[1]+=h1v*y0.y; acc[2] +=h1v*y0.z; acc[3] +=h1v*y0.w;
        acc[4]+=h2v*y1.x; acc[5]+=h2v*y1.y; acc[6] +=h2v*y1.z; acc[7] +=h2v*y1.w;
        acc[8]+=h2v*y2.x; acc[9]+=h3v*y2.y; acc[10]+=h3v*y2.z; acc[11]+=h3v*y2.w;
        acc[12]+=h3v*y3.x; acc[13]+=h3v*y3.y; acc[14]+=h3v*y3.z; acc[15]+=h3v*y3.w;
    }
    const float inv16 = 0.0625f;
    float4* o = (float4*)(g_agg + (size_t)gw*512 + c*16);
    o[0]=make_float4(acc[0]*inv16, acc[1]*inv16, acc[2]*inv16, acc[3]*inv16);
    o[1]=make_float4(acc[4]*inv16, acc[5]*inv16, acc[6]*inv16, acc[7]*inv16);
    o[2]=make_float4(acc[8]*inv16, acc[9]*inv16, acc[10]*inv16, acc[11]*inv16);
    o[3]=make_float4(acc[12]*inv16, acc[13]*inv16, acc[14]*inv16, acc[15]*inv16);
}

// ---------------- 8: node update (warp per node, lane = k) ----------------
__global__ void k_node(const float* __restrict__ W_lmix, const float* __restrict__ W_scm,
                       const float* __restrict__ gsc,   const float* __restrict__ W_prod,
                       const float* __restrict__ W_hid, const int* __restrict__ types, int t) {
    int gw = (blockIdx.x*blockDim.x + threadIdx.x) >> 5;
    if (gw >= NN) return;
    int k = threadIdx.x & 31;
    int type = types[gw];
    float gsck = gsc[t*320 + type*32 + k];
    const float* wp = W_prod + t*960 + type*96;
    float w0 = wp[k], w1 = wp[32+k], w2 = wp[64+k];
    const float* agg_n = g_agg + (size_t)gw*512;
    float* nf_n = g_nf + (size_t)gw*512;
    float s = 0.f, mul = 0.f;
#pragma unroll 1
    for (int L=0; L<16; L++) {
        int l = (L==0) ? 0 : ((L<4) ? 1 : ((L<9) ? 2 : 3));
        const float* wl = W_lmix + t*4096 + l*1024;
        const float* ws = W_scm  + t*4096 + l*1024;
        const float* wh = W_hid  + t*4096 + l*1024;
        float m = 0.f, sv = 0.f;
#pragma unroll
        for (int c=0;c<32;c++) {
            float av = agg_n[c*16 + L];
            float nv = nf_n[c*16 + L];
            m  += av * wl[c*32 + k];
            sv += nv * ws[c*32 + k];
        }
        sv *= gsck;
        if (L == 0) { s = m; mul = w0 + s*w1 + s*s*w2; }
        float pf = m * mul;
        float acc = sv;
#pragma unroll
        for (int c=0;c<32;c++) {
            float pfc = __shfl_sync(0xffffffffu, pf, c);
            acc += pfc * wh[c*32 + k];
        }
        nf_n[k*16 + L] = acc;   // all lanes' reads of this L happened above (shfl = warp sync)
        if (L == 0) g_nf0[gw*32 + k] = acc;
    }
}

// ---------------- 9: node readout ----------------
__global__ void k_nodeout(const float* __restrict__ W_node, float* __restrict__ out, int t) {
    int idx = blockIdx.x*blockDim.x + threadIdx.x;
    if (idx >= NN*100) return;
    int n = idx / 100;
    int j = idx - n*100;
    const float* wn = W_node + t*3200;
    const float* nf0 = g_nf0 + n*32;
    float a = 0.f;
#pragma unroll
    for (int c=0;c<32;c++) a += nf0[c] * wn[c*100 + j];
    out[O_NC + (size_t)idx*2 + t] = a;
    float* osum = out + O_NSUM + idx;
    if (t == 0) *osum = a; else *osum = *osum + a;
}

// ---------------- 10: edge readout (warp per edge, lane = channel) ----------------
__global__ void k_edge(const int* __restrict__ ei, const float* __restrict__ W_er,
                       const float* __restrict__ W_edge, float* __restrict__ out, int t) {
    int gw = (blockIdx.x*blockDim.x + threadIdx.x) >> 5;
    if (gw >= EE) return;
    int lane = threadIdx.x & 31;
    int e = gw;
    int s = ei[e], d = ei[EE+e];
    const float4* ebv = (const float4*)(g_eb + (size_t)e*8);
    float4 b0 = ebv[0], b1 = ebv[1];
    const float* wer = W_er + t*256;
    float a = b0.x*wer[lane]      + b0.y*wer[32+lane]  + b0.z*wer[64+lane]  + b0.w*wer[96+lane]
            + b1.x*wer[128+lane]  + b1.y*wer[160+lane] + b1.z*wer[192+lane] + b1.w*wer[224+lane];
    float Re = silu_f(a);
    const float4* yv = (const float4*)(g_Y + (size_t)e*16);
    float4 y0=yv[0], y1=yv[1], y2=yv[2], y3=yv[3];
    const float4* ns = (const float4*)(g_nf + (size_t)s*512 + lane*16);
    const float4* nd = (const float4*)(g_nf + (size_t)d*512 + lane*16);
    float4 s0=ns[0], s1=ns[1], s2=ns[2], s3=ns[3];
    float4 d0=nd[0], d1=nd[1], d2=nd[2], d3=nd[3];
    float inv =
        (s0.x+d0.x)*y0.x + (s0.y+d0.y)*y0.y + (s0.z+d0.z)*y0.z + (s0.w+d0.w)*y0.w +
        (s1.x+d1.x)*y1.x + (s1.y+d1.y)*y1.y + (s1.z+d1.z)*y1.z + (s1.w+d1.w)*y1.w +
        (s2.x+d2.x)*y2.x + (s2.y+d2.y)*y2.y + (s2.z+d2.z)*y2.z + (s2.w+d2.w)*y2.w +
        (s3.x+d3.x)*y3.x + (s3.y+d3.y)*y3.y + (s3.z+d3.z)*y3.z + (s3.w+d3.w)*y3.w;
    float q = inv * Re;
    const float* We = W_edge + t*3200;
    float a0=0.f, a1=0.f, a2=0.f, a3=0.f;
#pragma unroll
    for (int c=0;c<32;c++) {
        float qc = __shfl_sync(0xffffffffu, q, c);
        const float* row = We + c*100;
        a0 += qc*row[lane];
        a1 += qc*row[lane+32];
        a2 += qc*row[lane+64];
        if (lane < 4) a3 += qc*row[lane+96];
    }
    size_t b = (size_t)e*100;
    float* oc   = out + O_EC;
    float* osum = out + O_ESUM;
    oc[(b+lane)*2+t]    = a0;
    oc[(b+lane+32)*2+t] = a1;
    oc[(b+lane+64)*2+t] = a2;
    if (lane < 4) oc[(b+lane+96)*2+t] = a3;
    if (t == 0) {
        osum[b+lane]=a0; osum[b+lane+32]=a1; osum[b+lane+64]=a2;
        if (lane < 4) osum[b+lane+96]=a3;
    } else {
        osum[b+lane]+=a0; osum[b+lane+32]+=a1; osum[b+lane+64]+=a2;
        if (lane < 4) osum[b+lane+96]+=a3;
    }
}

// ---------------- launch ----------------
extern "C" void kernel_launch(void* const* d_in, const int* in_sizes, int n_in,
                              void* d_out, int out_size) {
    const float* positions = (const float*)d_in[0];
    // d_in[1] = node_attrs (one-hot of node_types; unused — we use node_types directly)
    const float* shifts = (const float*)d_in[2];
    const float* W_emb  = (const float*)d_in[3];
    const float* rW1    = (const float*)d_in[4];
    const float* rb1    = (const float*)d_in[5];
    const float* rW2    = (const float*)d_in[6];
    const float* rb2    = (const float*)d_in[7];
    const float* rW3    = (const float*)d_in[8];
    const float* W_up   = (const float*)d_in[9];
    const float* W_lmix = (const float*)d_in[10];
    const float* W_scm  = (const float*)d_in[11];
    const float* gsc    = (const float*)d_in[12];
    const float* W_prod = (const float*)d_in[13];
    const float* W_hid  = (const float*)d_in[14];
    const float* W_node = (const float*)d_in[15];
    const float* W_edge = (const float*)d_in[16];
    const float* W_er   = (const float*)d_in[17];
    const int*   ei     = (const int*)d_in[18];
    const int*   types  = (const int*)d_in[19];
    float* out = (float*)d_out;

    const int SMEM_RADIAL = 21184 * 4; // 84,736 B dynamic smem
    static int smem_set = 0;
    if (!smem_set) {
        cudaFuncSetAttribute(k_radial, cudaFuncAttributeMaxDynamicSharedMemorySize, SMEM_RADIAL);
        smem_set = 1;
    }

    k_zero_deg<<<(NN+255)/256, 256>>>();
    k_geom<<<EE/256, 256>>>(positions, shifts, ei);
    k_scan<<<1, 1024>>>();
    k_scatter<<<EE/256, 256>>>(ei);
    k_init_nf<<<(NN*32)/256, 256>>>(W_emb, types);

    for (int t = 0; t < TT; t++) {
        k_h0<<<(NN*32)/256, 256>>>(W_up, t);
        k_radial<<<EE/128, 128, SMEM_RADIAL>>>(rW1, rb1, rW2, rb2, rW3, t);
        k_gather<<<(NN*32)/256, 256>>>(ei);
        k_node<<<(NN*32)/256, 256>>>(W_lmix, W_scm, gsc, W_prod, W_hid, types, t);
        k_nodeout<<<(NN*100 + 255)/256, 256>>>(W_node, out, t);
        k_edge<<<(EE*32)/256, 256>>>(ei, W_er, W_edge, out, t);
    }
}

// round 3
// speedup vs baseline: 1.2022x; 1.2022x over previous
#include <cuda_runtime.h>
#include <math.h>

typedef unsigned long long ull;

// Problem constants (fixed shapes)
#define NN 20000
#define EE 320000

// Output layout offsets (floats)
#define O_NSUM 0
#define O_NC   (NN*100)
#define O_ESUM (NN*100 + NN*100*2)
#define O_EC   (O_ESUM + (size_t)EE*100)

// ---------------- scratch (static device arrays; no allocation) ----------------
static __device__ float g_Y [(size_t)EE*16];
static __device__ float g_eb[(size_t)EE*8];
static __device__ float g_R4[(size_t)EE*128];
static __device__ float g_h0[NN*32];
static __device__ float g_nf [(size_t)NN*512];   // [n][c][L]
static __device__ float g_agg[(size_t)NN*512];   // [n][c][L]
static __device__ float g_nf0[2*NN*32];          // [t][n][k]
static __device__ float g_q  [(size_t)2*EE*32];  // [t][e][c]
static __device__ int   g_deg[NN];
static __device__ int   g_off[NN+1];
static __device__ int   g_cur[NN];
static __device__ int   g_eids[EE];

__device__ __forceinline__ float silu_f(float x) { return x / (1.f + __expf(-x)); }

__device__ __forceinline__ ull ffma2(ull a, ull b, ull c) {
    ull d;
    asm("fma.rn.f32x2 %0, %1, %2, %3;" : "=l"(d) : "l"(a), "l"(b), "l"(c));
    return d;
}
__device__ __forceinline__ ull pack2(float x, float y) {
    ull r; asm("mov.b64 %0, {%1, %2};" : "=l"(r) : "f"(x), "f"(y)); return r;
}
__device__ __forceinline__ float2 unpack2(ull v) {
    float2 r; asm("mov.b64 {%0, %1}, %2;" : "=f"(r.x), "=f"(r.y) : "l"(v)); return r;
}

// ---------------- 0: zero degree ----------------
__global__ void k_zero_deg() {
    int i = blockIdx.x*blockDim.x + threadIdx.x;
    if (i < NN) g_deg[i] = 0;
}

// ---------------- 1: edge geometry ----------------
__global__ void k_geom(const float* __restrict__ pos, const float* __restrict__ shifts,
                       const int* __restrict__ ei) {
    int e = blockIdx.x*blockDim.x + threadIdx.x;
    if (e >= EE) return;
    int s = ei[e], d = ei[EE+e];
    float vx = pos[d*3+0] - pos[s*3+0] + shifts[e*3+0];
    float vy = pos[d*3+1] - pos[s*3+1] + shifts[e*3+1];
    float vz = pos[d*3+2] - pos[s*3+2] + shifts[e*3+2];
    float r = sqrtf(vx*vx + vy*vy + vz*vz) + 1e-9f;
    float inr = 1.f/r;
    float x = vx*inr, y = vy*inr, z = vz*inr;
    const float s3=1.7320508075688772f, s5=2.23606797749979f, s15=3.872983346207417f,
                s7=2.6457513110645907f, c358=2.091650066335189f, c105=10.246950765959598f,
                c218=1.6201851746019651f;
    float z2=z*z, x2=x*x, y2=y*y;
    float Y[16];
    Y[0]=1.f;               Y[1]=s3*x;              Y[2]=s3*y;               Y[3]=s3*z;
    Y[4]=s15*x*y;           Y[5]=s15*y*z;           Y[6]=0.5f*s5*(3.f*z2-1.f); Y[7]=s15*x*z;
    Y[8]=0.5f*s15*(x2-y2);  Y[9]=c358*y*(3.f*x2-y2); Y[10]=c105*x*y*z;
    Y[11]=c218*y*(5.f*z2-1.f); Y[12]=0.5f*s7*z*(5.f*z2-3.f); Y[13]=c218*x*(5.f*z2-1.f);
    Y[14]=0.5f*c105*z*(x2-y2); Y[15]=c358*x*(x2-3.f*y2);
    float4* yo = (float4*)(g_Y + (size_t)e*16);
    yo[0]=make_float4(Y[0],Y[1],Y[2],Y[3]);
    yo[1]=make_float4(Y[4],Y[5],Y[6],Y[7]);
    yo[2]=make_float4(Y[8],Y[9],Y[10],Y[11]);
    yo[3]=make_float4(Y[12],Y[13],Y[14],Y[15]);
    float xr = r*0.2f;
    float cut = 0.f;
    if (xr < 1.f) {
        float x2c = xr*xr;
        float x5 = x2c*x2c*xr;
        cut = 1.f - 21.f*x5 + 35.f*x5*xr - 15.f*x5*x2c;
    }
    float pref = 0.6324555320336759f * inr * cut;
    float w = 0.6283185307179586f * r;
    float eb[8];
#pragma unroll
    for (int n=0;n<8;n++) eb[n] = pref * sinf((float)(n+1)*w);
    float4* eo = (float4*)(g_eb + (size_t)e*8);
    eo[0]=make_float4(eb[0],eb[1],eb[2],eb[3]);
    eo[1]=make_float4(eb[4],eb[5],eb[6],eb[7]);
    atomicAdd(&g_deg[d], 1);
}

// ---------------- 2: exclusive scan (single block) ----------------
__global__ void k_scan() {
    __shared__ int sdata[1024];
    __shared__ int s_carry;
    int tid = threadIdx.x;
    if (tid == 0) { s_carry = 0; g_off[0] = 0; }
    __syncthreads();
    for (int base = 0; base < NN; base += 1024) {
        int i = base + tid;
        int v = (i < NN) ? g_deg[i] : 0;
        sdata[tid] = v;
        __syncthreads();
        for (int o = 1; o < 1024; o <<= 1) {
            int add = (tid >= o) ? sdata[tid - o] : 0;
            __syncthreads();
            sdata[tid] += add;
            __syncthreads();
        }
        int carry = s_carry;
        if (i < NN) {
            int incl = sdata[tid];
            g_off[i+1] = carry + incl;
            g_cur[i]   = carry + incl - v;
        }
        __syncthreads();
        if (tid == 0) s_carry = carry + sdata[1023];
        __syncthreads();
    }
}

// ---------------- 3: scatter edge ids into CSR ----------------
__global__ void k_scatter(const int* __restrict__ ei) {
    int e = blockIdx.x*blockDim.x + threadIdx.x;
    if (e >= EE) return;
    int d = ei[EE+e];
    int pos = atomicAdd(&g_cur[d], 1);
    g_eids[pos] = e;
}

// ---------------- 4: init node features ----------------
__global__ void k_init_nf(const float* __restrict__ W_emb, const int* __restrict__ types) {
    int idx = blockIdx.x*blockDim.x + threadIdx.x;
    if (idx >= NN*32) return;
    int n = idx >> 5, c = idx & 31;
    float v = W_emb[types[n]*32 + c];
    float4* o = (float4*)(g_nf + (size_t)n*512 + c*16);
    o[0] = make_float4(v,0.f,0.f,0.f);
    o[1] = make_float4(0.f,0.f,0.f,0.f);
    o[2] = o[1]; o[3] = o[1];
}

// ---------------- 5: h0 (warp per node) ----------------
__global__ void k_h0(const float* __restrict__ W_up, int t) {
    int gw = (blockIdx.x*blockDim.x + threadIdx.x) >> 5;
    if (gw >= NN) return;
    int k = threadIdx.x & 31;
    const float* wu = W_up + t*1024;
    const float* nf = g_nf + (size_t)gw*512;
    float a = 0.f;
#pragma unroll
    for (int c=0;c<32;c++) a += nf[c*16] * wu[c*32 + k];
    g_h0[gw*32 + k] = a;
}

// ---------------- 6: radial MLP with f32x2 packed FMA ----------------
__global__ void __launch_bounds__(128) k_radial(
        const float* __restrict__ rW1, const float* __restrict__ rb1,
        const float* __restrict__ rW2, const float* __restrict__ rb2,
        const float* __restrict__ rW3, int t) {
    extern __shared__ float sh[];
    float* s_w1 = sh;            // 512
    float* s_b1 = s_w1 + 512;    // 64
    float* s_w2 = s_b1 + 64;     // 4096
    float* s_b2 = s_w2 + 4096;   // 64
    float* s_w3 = s_b2 + 64;     // 8192
    float* s_x  = s_w3 + 8192;   // 64*129
    int tid = threadIdx.x;
    for (int i=tid;i<512;i+=128)  s_w1[i]=rW1[t*512+i];
    for (int i=tid;i<64;i+=128)   s_b1[i]=rb1[t*64+i];
    for (int i=tid;i<4096;i+=128) s_w2[i]=rW2[t*4096+i];
    for (int i=tid;i<64;i+=128)   s_b2[i]=rb2[t*64+i];
    for (int i=tid;i<8192;i+=128) s_w3[i]=rW3[t*8192+i];
    __syncthreads();

    int e = blockIdx.x*128 + tid;
    const float4* ebv = (const float4*)(g_eb + (size_t)e*8);
    float4 e0 = ebv[0], e1 = ebv[1];
    float ebl[8] = {e0.x,e0.y,e0.z,e0.w,e1.x,e1.y,e1.z,e1.w};

    ull acc2[32];
    // layer 1: 8 -> 64 (f32x2)
    {
        const ull* bp = (const ull*)s_b1;
#pragma unroll
        for (int j=0;j<32;j++) acc2[j] = bp[j];
#pragma unroll
        for (int b=0;b<8;b++) {
            ull vv = pack2(ebl[b], ebl[b]);
            const ulonglong2* w = (const ulonglong2*)(s_w1 + b*64);
#pragma unroll
            for (int j=0;j<16;j++) {
                ulonglong2 ww = w[j];
                acc2[2*j]   = ffma2(vv, ww.x, acc2[2*j]);
                acc2[2*j+1] = ffma2(vv, ww.y, acc2[2*j+1]);
            }
        }
#pragma unroll
        for (int j=0;j<32;j++) {
            float2 p = unpack2(acc2[j]);
            s_x[(2*j)*129+tid]   = silu_f(p.x);
            s_x[(2*j+1)*129+tid] = silu_f(p.y);
        }
    }
    // layer 2: 64 -> 64 (f32x2)
    {
        const ull* bp = (const ull*)s_b2;
#pragma unroll
        for (int j=0;j<32;j++) acc2[j] = bp[j];
        for (int i=0;i<64;i++) {
            float v = s_x[i*129+tid];
            ull vv = pack2(v, v);
            const ulonglong2* w = (const ulonglong2*)(s_w2 + i*64);
#pragma unroll
            for (int j=0;j<16;j++) {
                ulonglong2 ww = w[j];
                acc2[2*j]   = ffma2(vv, ww.x, acc2[2*j]);
                acc2[2*j+1] = ffma2(vv, ww.y, acc2[2*j+1]);
            }
        }
        float xl[64];
#pragma unroll
        for (int j=0;j<32;j++) {
            float2 p = unpack2(acc2[j]);
            xl[2*j] = silu_f(p.x); xl[2*j+1] = silu_f(p.y);
        }
#pragma unroll
        for (int j=0;j<64;j++) s_x[j*129+tid] = xl[j];
    }
    // layer 3: 64 -> 128, two halves of 64 outputs (f32x2)
#pragma unroll 2
    for (int half=0; half<2; half++) {
#pragma unroll
        for (int j=0;j<32;j++) acc2[j] = 0ULL;
        for (int i=0;i<64;i++) {
            float v = s_x[i*129+tid];
            ull vv = pack2(v, v);
            const ulonglong2* w = (const ulonglong2*)(s_w3 + i*128 + half*64);
#pragma unroll
            for (int j=0;j<16;j++) {
                ulonglong2 ww = w[j];
                acc2[2*j]   = ffma2(vv, ww.x, acc2[2*j]);
                acc2[2*j+1] = ffma2(vv, ww.y, acc2[2*j+1]);
            }
        }
        float4* op = (float4*)(g_R4 + (size_t)e*128 + half*64);
#pragma unroll
        for (int q=0;q<16;q++) {
            float2 a = unpack2(acc2[2*q]);
            float2 b = unpack2(acc2[2*q+1]);
            op[q] = make_float4(a.x, a.y, b.x, b.y);
        }
    }
}

// ---------------- 7: aggregation gather (warp per dst node) ----------------
__global__ void k_gather(const int* __restrict__ ei) {
    int gw = (blockIdx.x*blockDim.x + threadIdx.x) >> 5;
    if (gw >= NN) return;
    int c = threadIdx.x & 31;
    float acc[16];
#pragma unroll
    for (int L=0;L<16;L++) acc[L]=0.f;
    int beg = g_off[gw], end = g_off[gw+1];
    for (int idx = beg; idx < end; idx++) {
        int e = g_eids[idx];
        int s = ei[e];
        float hs = g_h0[s*32 + c];
        const float4* yv = (const float4*)(g_Y + (size_t)e*16);
        float4 y0=yv[0], y1=yv[1], y2=yv[2], y3=yv[3];
        const float* R = g_R4 + (size_t)e*128;
        float h0v = hs*R[c], h1v = hs*R[32+c], h2v = hs*R[64+c], h3v = hs*R[96+c];
        acc[0]+=h0v*y0.x; acc[1]+=h1v*y0.y; acc[2] +=h1v*y0.z; acc[3] +=h1v*y0.w;
        acc[4]+=h2v*y1.x; acc[5]+=h2v*y1.y; acc[6] +=h2v*y1.z; acc[7] +=h2v*y1.w;
        acc[8]+=h2v*y2.x; acc[9]+=h3v*y2.y; acc[10]+=h3v*y2.z; acc[11]+=h3v*y2.w;
        acc[12]+=h3v*y3.x; acc[13]+=h3v*y3.y; acc[14]+=h3v*y3.z; acc[15]+=h3v*y3.w;
    }
    const float inv16 = 0.0625f;
    float4* o = (float4*)(g_agg + (size_t)gw*512 + c*16);
    o[0]=make_float4(acc[0]*inv16, acc[1]*inv16, acc[2]*inv16, acc[3]*inv16);
    o[1]=make_float4(acc[4]*inv16, acc[5]*inv16, acc[6]*inv16, acc[7]*inv16);
    o[2]=make_float4(acc[8]*inv16, acc[9]*inv16, acc[10]*inv16, acc[11]*inv16);
    o[3]=make_float4(acc[12]*inv16, acc[13]*inv16, acc[14]*inv16, acc[15]*inv16);
}

// ---------------- 8: node update (smem-staged weights, warp per node) ----------------
__global__ void __launch_bounds__(256) k_node(
        const float* __restrict__ W_lmix, const float* __restrict__ W_scm,
        const float* __restrict__ gsc,    const float* __restrict__ W_prod,
        const float* __restrict__ W_hid,  const int* __restrict__ types, int t) {
    __shared__ float s_wl[4096];
    __shared__ float s_ws[4096];
    __shared__ float s_wh[4096];
    int tid = threadIdx.x;
    {
        const float4* a = (const float4*)(W_lmix + t*4096);
        const float4* b = (const float4*)(W_scm  + t*4096);
        const float4* c = (const float4*)(W_hid  + t*4096);
        for (int i=tid;i<1024;i+=256) {
            ((float4*)s_wl)[i] = a[i];
            ((float4*)s_ws)[i] = b[i];
            ((float4*)s_wh)[i] = c[i];
        }
    }
    __syncthreads();
    int gw = blockIdx.x*8 + (tid>>5);
    if (gw >= NN) return;
    int k = tid & 31;
    int type = types[gw];
    float gsck = gsc[t*320 + type*32 + k];
    const float* wp = W_prod + t*960 + type*96;
    float w0 = wp[k], w1 = wp[32+k], w2 = wp[64+k];
    const float4* agg4 = (const float4*)(g_agg + (size_t)gw*512);
    const float4* nf4  = (const float4*)(g_nf  + (size_t)gw*512);

    float m[16], sv[16];
#pragma unroll
    for (int L=0;L<16;L++) { m[L]=0.f; sv[L]=0.f; }
#pragma unroll 4
    for (int c=0;c<32;c++) {
        float4 A0 = agg4[c*4+0], A1 = agg4[c*4+1], A2 = agg4[c*4+2], A3 = agg4[c*4+3];
        float4 N0 = nf4 [c*4+0], N1 = nf4 [c*4+1], N2 = nf4 [c*4+2], N3 = nf4 [c*4+3];
        int cw = c*32 + k;
        float wl0 = s_wl[cw], wl1 = s_wl[1024+cw], wl2 = s_wl[2048+cw], wl3 = s_wl[3072+cw];
        float ws0 = s_ws[cw], ws1 = s_ws[1024+cw], ws2 = s_ws[2048+cw], ws3 = s_ws[3072+cw];
        m[0] += A0.x*wl0;
        m[1] += A0.y*wl1;  m[2] += A0.z*wl1;  m[3] += A0.w*wl1;
        m[4] += A1.x*wl2;  m[5] += A1.y*wl2;  m[6] += A1.z*wl2;  m[7] += A1.w*wl2;
        m[8] += A2.x*wl2;
        m[9] += A2.y*wl3;  m[10]+= A2.z*wl3;  m[11]+= A2.w*wl3;
        m[12]+= A3.x*wl3;  m[13]+= A3.y*wl3;  m[14]+= A3.z*wl3;  m[15]+= A3.w*wl3;
        sv[0] += N0.x*ws0;
        sv[1] += N0.y*ws1;  sv[2] += N0.z*ws1;  sv[3] += N0.w*ws1;
        sv[4] += N1.x*ws2;  sv[5] += N1.y*ws2;  sv[6] += N1.z*ws2;  sv[7] += N1.w*ws2;
        sv[8] += N2.x*ws2;
        sv[9] += N2.y*ws3;  sv[10]+= N2.z*ws3;  sv[11]+= N2.w*ws3;
        sv[12]+= N3.x*ws3;  sv[13]+= N3.y*ws3;  sv[14]+= N3.z*ws3;  sv[15]+= N3.w*ws3;
    }
    float s = m[0];
    float mul = w0 + s*w1 + s*s*w2;
    float pf[16], acc[16];
#pragma unroll
    for (int L=0;L<16;L++) { pf[L] = m[L]*mul; acc[L] = sv[L]*gsck; }
#pragma unroll 4
    for (int c=0;c<32;c++) {
        int cw = c*32 + k;
        float wh0 = s_wh[cw], wh1 = s_wh[1024+cw], wh2 = s_wh[2048+cw], wh3 = s_wh[3072+cw];
        acc[0] += __shfl_sync(0xffffffffu, pf[0], c)*wh0;
        acc[1] += __shfl_sync(0xffffffffu, pf[1], c)*wh1;
        acc[2] += __shfl_sync(0xffffffffu, pf[2], c)*wh1;
        acc[3] += __shfl_sync(0xffffffffu, pf[3], c)*wh1;
        acc[4] += __shfl_sync(0xffffffffu, pf[4], c)*wh2;
        acc[5] += __shfl_sync(0xffffffffu, pf[5], c)*wh2;
        acc[6] += __shfl_sync(0xffffffffu, pf[6], c)*wh2;
        acc[7] += __shfl_sync(0xffffffffu, pf[7], c)*wh2;
        acc[8] += __shfl_sync(0xffffffffu, pf[8], c)*wh2;
        acc[9] += __shfl_sync(0xffffffffu, pf[9], c)*wh3;
        acc[10]+= __shfl_sync(0xffffffffu, pf[10],c)*wh3;
        acc[11]+= __shfl_sync(0xffffffffu, pf[11],c)*wh3;
        acc[12]+= __shfl_sync(0xffffffffu, pf[12],c)*wh3;
        acc[13]+= __shfl_sync(0xffffffffu, pf[13],c)*wh3;
        acc[14]+= __shfl_sync(0xffffffffu, pf[14],c)*wh3;
        acc[15]+= __shfl_sync(0xffffffffu, pf[15],c)*wh3;
    }
    float4* nfo = (float4*)(g_nf + (size_t)gw*512 + k*16);
    nfo[0] = make_float4(acc[0], acc[1], acc[2], acc[3]);
    nfo[1] = make_float4(acc[4], acc[5], acc[6], acc[7]);
    nfo[2] = make_float4(acc[8], acc[9], acc[10], acc[11]);
    nfo[3] = make_float4(acc[12], acc[13], acc[14], acc[15]);
    g_nf0[t*NN*32 + gw*32 + k] = acc[0];
}

// ---------------- 9: edge q = inv * Re (warp per edge) ----------------
__global__ void k_edge_q(const int* __restrict__ ei, const float* __restrict__ W_er, int t) {
    __shared__ float s_wer[256];
    int tid = threadIdx.x;
    s_wer[tid] = W_er[t*256 + tid];
    __syncthreads();
    int gw = blockIdx.x*8 + (tid>>5);
    if (gw >= EE) return;
    int lane = tid & 31;
    int e = gw;
    int s = ei[e], d = ei[EE+e];
    const float4* ebv = (const float4*)(g_eb + (size_t)e*8);
    float4 b0 = ebv[0], b1 = ebv[1];
    float a = b0.x*s_wer[lane]     + b0.y*s_wer[32+lane]  + b0.z*s_wer[64+lane]  + b0.w*s_wer[96+lane]
            + b1.x*s_wer[128+lane] + b1.y*s_wer[160+lane] + b1.z*s_wer[192+lane] + b1.w*s_wer[224+lane];
    float Re = silu_f(a);
    const float4* yv = (const float4*)(g_Y + (size_t)e*16);
    float4 y0=yv[0], y1=yv[1], y2=yv[2], y3=yv[3];
    const float4* ns = (const float4*)(g_nf + (size_t)s*512 + lane*16);
    const float4* nd = (const float4*)(g_nf + (size_t)d*512 + lane*16);
    float4 s0=ns[0], s1=ns[1], s2=ns[2], s3=ns[3];
    float4 d0=nd[0], d1=nd[1], d2=nd[2], d3=nd[3];
    float inv =
        (s0.x+d0.x)*y0.x + (s0.y+d0.y)*y0.y + (s0.z+d0.z)*y0.z + (s0.w+d0.w)*y0.w +
        (s1.x+d1.x)*y1.x + (s1.y+d1.y)*y1.y + (s1.z+d1.z)*y1.z + (s1.w+d1.w)*y1.w +
        (s2.x+d2.x)*y2.x + (s2.y+d2.y)*y2.y + (s2.z+d2.z)*y2.z + (s2.w+d2.w)*y2.w +
        (s3.x+d3.x)*y3.x + (s3.y+d3.y)*y3.y + (s3.z+d3.z)*y3.z + (s3.w+d3.w)*y3.w;
    g_q[(size_t)t*EE*32 + (size_t)e*32 + lane] = inv * Re;
}

// ---------------- 10: tiled projection GEMM: [M,32] x [32,100] for both t ----------------
// which=0: src = g_nf0 (node), which=1: src = g_q (edge)
#define PROJ_TE 64
__global__ void __launch_bounds__(320) k_proj(int which, const float* __restrict__ W,
                                              float* __restrict__ out,
                                              size_t contrib_off, size_t sum_off, int M) {
    extern __shared__ float sm[];
    float* s_q = sm;             // [2][32][65]  = 4160 floats
    float* s_w = sm + 4160;      // [2][3200]    = 6400 floats
    const float* src = which ? g_q : g_nf0;
    size_t tstride = which ? (size_t)EE*32 : (size_t)NN*32;
    int tid = threadIdx.x;
    int base = blockIdx.x*PROJ_TE;
    for (int i=tid;i<6400;i+=320) s_w[i] = W[i];
    for (int idx=tid; idx<2*PROJ_TE*32; idx+=320) {
        int tt  = idx >> 11;       // /(64*32)
        int rem = idx & 2047;
        int el  = rem >> 5;
        int c   = rem & 31;
        int m_  = base + el;
        float v = (m_ < M) ? src[tt*tstride + (size_t)m_*32 + c] : 0.f;
        s_q[tt*2080 + c*65 + el] = v;
    }
    __syncthreads();
    int te = tid & 31;
    int tj = tid >> 5;       // 0..9
    int j0base = tj*10;
    ull a0[2][5], a1[2][5];
#pragma unroll
    for (int re=0;re<2;re++)
#pragma unroll
        for (int pp=0;pp<5;pp++) { a0[re][pp]=0ULL; a1[re][pp]=0ULL; }
    for (int c=0;c<32;c++) {
        float q00 = s_q[c*65 + te];
        float q01 = s_q[c*65 + te + 32];
        float q10 = s_q[2080 + c*65 + te];
        float q11 = s_q[2080 + c*65 + te + 32];
        ull v00 = pack2(q00,q00), v01 = pack2(q01,q01);
        ull v10 = pack2(q10,q10), v11 = pack2(q11,q11);
        const ull* w0 = (const ull*)(s_w + c*100 + j0base);
        const ull* w1 = (const ull*)(s_w + 3200 + c*100 + j0base);
#pragma unroll
        for (int pp=0;pp<5;pp++) {
            ull ww0 = w0[pp], ww1 = w1[pp];
            a0[0][pp] = ffma2(v00, ww0, a0[0][pp]);
            a0[1][pp] = ffma2(v01, ww0, a0[1][pp]);
            a1[0][pp] = ffma2(v10, ww1, a1[0][pp]);
            a1[1][pp] = ffma2(v11, ww1, a1[1][pp]);
        }
    }
    float* oc = out + contrib_off;
    float* os = out + sum_off;
#pragma unroll
    for (int re=0;re<2;re++) {
        int m_ = base + te + 32*re;
        if (m_ >= M) continue;
        size_t b = (size_t)m_*100;
#pragma unroll
        for (int pp=0;pp<5;pp++) {
            int j0 = j0base + 2*pp;
            float2 p0 = unpack2(a0[re][pp]);
            float2 p1 = unpack2(a1[re][pp]);
            *(float4*)(oc + (b + j0)*2) = make_float4(p0.x, p1.x, p0.y, p1.y);
            *(float2*)(os + b + j0)     = make_float2(p0.x+p1.x, p0.y+p1.y);
        }
    }
}

// ---------------- launch ----------------
extern "C" void kernel_launch(void* const* d_in, const int* in_sizes, int n_in,
                              void* d_out, int out_size) {
    const float* positions = (const float*)d_in[0];
    const float* shifts = (const float*)d_in[2];
    const float* W_emb  = (const float*)d_in[3];
    const float* rW1    = (const float*)d_in[4];
    const float* rb1    = (const float*)d_in[5];
    const float* rW2    = (const float*)d_in[6];
    const float* rb2    = (const float*)d_in[7];
    const float* rW3    = (const float*)d_in[8];
    const float* W_up   = (const float*)d_in[9];
    const float* W_lmix = (const float*)d_in[10];
    const float* W_scm  = (const float*)d_in[11];
    const float* gsc    = (const float*)d_in[12];
    const float* W_prod = (const float*)d_in[13];
    const float* W_hid  = (const float*)d_in[14];
    const float* W_node = (const float*)d_in[15];
    const float* W_edge = (const float*)d_in[16];
    const float* W_er   = (const float*)d_in[17];
    const int*   ei     = (const int*)d_in[18];
    const int*   types  = (const int*)d_in[19];
    float* out = (float*)d_out;

    const int SMEM_RADIAL = 21184 * 4; // 84,736 B
    const int SMEM_PROJ   = 10560 * 4; // 42,240 B
    static int smem_set = 0;
    if (!smem_set) {
        cudaFuncSetAttribute(k_radial, cudaFuncAttributeMaxDynamicSharedMemorySize, SMEM_RADIAL);
        smem_set = 1;
    }

    k_zero_deg<<<(NN+255)/256, 256>>>();
    k_geom<<<EE/256, 256>>>(positions, shifts, ei);
    k_scan<<<1, 1024>>>();
    k_scatter<<<EE/256, 256>>>(ei);
    k_init_nf<<<(NN*32)/256, 256>>>(W_emb, types);

    for (int t = 0; t < 2; t++) {
        k_h0<<<(NN*32)/256, 256>>>(W_up, t);
        k_radial<<<EE/128, 128, SMEM_RADIAL>>>(rW1, rb1, rW2, rb2, rW3, t);
        k_gather<<<(NN*32)/256, 256>>>(ei);
        k_node<<<NN/8, 256>>>(W_lmix, W_scm, gsc, W_prod, W_hid, types, t);
        k_edge_q<<<EE/8, 256>>>(ei, W_er, t);
    }
    k_proj<<<(NN + PROJ_TE-1)/PROJ_TE, 320, SMEM_PROJ>>>(0, W_node, out, O_NC, O_NSUM, NN);
    k_proj<<<(EE + PROJ_TE-1)/PROJ_TE, 320, SMEM_PROJ>>>(1, W_edge, out, O_EC, O_ESUM, EE);
}